// round 5
// baseline (speedup 1.0000x reference)
#include <cuda_runtime.h>
#include <cstdint>

#define BB  512
#define TT  512
#define HH  128
#define G4  512
#define NIN 18

typedef unsigned long long ull;

// ---------------- scratch (device globals: allocation-free) ----------------
__device__ float g_xp   [(size_t)TT * BB * G4]; // 536 MB, reused: xproj0 then xproj1
__device__ float g_h1   [(size_t)TT * BB * HH]; // 134 MB, layer-0 hidden sequence
__device__ float g_h2   [BB * HH];              // last hidden of layer 1
__device__ float g_wt0  [HH * G4];              // Whh0 transposed  [k][g]
__device__ float g_wt1  [HH * G4];              // Whh1 transposed  [k][g]
__device__ float g_wtih1[HH * G4];              // Wih1 transposed  [k][g]
__device__ float g_bsum1[G4];                   // bih1 + bhh1

// ---------------- helpers ----------------
__device__ __forceinline__ ull pack2(float lo, float hi) {
    ull r; asm("mov.b64 %0, {%1, %2};" : "=l"(r) : "f"(lo), "f"(hi)); return r;
}
__device__ __forceinline__ void unpack2(ull v, float& lo, float& hi) {
    asm("mov.b64 {%0, %1}, %2;" : "=f"(lo), "=f"(hi) : "l"(v));
}
__device__ __forceinline__ ull fma2(ull a, ull b, ull c) {
    ull d; asm("fma.rn.f32x2 %0, %1, %2, %3;" : "=l"(d) : "l"(a), "l"(b), "l"(c)); return d;
}
__device__ __forceinline__ float fsig(float x)  { return __fdividef(1.f, 1.f + __expf(-x)); }
__device__ __forceinline__ float ftanh(float x) { return __fdividef(2.f, 1.f + __expf(-2.f * x)) - 1.f; }

// ---------------- prep: transposes + fused layer-1 bias ----------------
__global__ void prep_kernel(const float* __restrict__ Whh0, const float* __restrict__ Whh1,
                            const float* __restrict__ Wih1, const float* __restrict__ bih1,
                            const float* __restrict__ bhh1) {
    int idx = blockIdx.x * 256 + threadIdx.x;
    if (idx < G4 * HH) {
        int g = idx / HH, k = idx % HH;
        g_wt0  [k * G4 + g] = Whh0[idx];
        g_wt1  [k * G4 + g] = Whh1[idx];
        g_wtih1[k * G4 + g] = Wih1[idx];
    }
    if (idx < G4) g_bsum1[idx] = bih1[idx] + bhh1[idx];
}

// ---------------- xproj0: g_xp[t][b][g] = x[b][t] . Wih0[g] + bih0[g] + bhh0[g] ----------------
__global__ void __launch_bounds__(256) xproj0_kernel(const float* __restrict__ x,
                                                     const float* __restrict__ Wih0,
                                                     const float* __restrict__ bih0,
                                                     const float* __restrict__ bhh0) {
    __shared__ float wst[NIN][G4];   // transposed for conflict-free reads
    __shared__ float bs[G4];
    __shared__ float xs[16][NIN];
    int tid = threadIdx.x;
    for (int i = tid; i < G4 * NIN; i += 256) {
        int g = i / NIN, d = i % NIN;
        wst[d][g] = Wih0[i];
    }
    for (int i = tid; i < G4; i += 256) bs[i] = bih0[i] + bhh0[i];
    int n0 = blockIdx.x * 16;        // n = t*BB + b
    for (int i = tid; i < 16 * NIN; i += 256) {
        int r = i / NIN, d = i % NIN;
        int n = n0 + r;
        int t = n >> 9, b = n & 511;
        xs[r][d] = x[((size_t)b * TT + t) * NIN + d];
    }
    __syncthreads();

    int gA = tid, gB = tid + 256;
    float wA[NIN], wB[NIN];
#pragma unroll
    for (int d = 0; d < NIN; d++) { wA[d] = wst[d][gA]; wB[d] = wst[d][gB]; }
    float bA = bs[gA], bBv = bs[gB];
    for (int r = 0; r < 16; r++) {
        float a0 = bA, a1 = bBv;
#pragma unroll
        for (int d = 0; d < NIN; d++) {
            float xv = xs[r][d];
            a0 += xv * wA[d];
            a1 += xv * wB[d];
        }
        size_t base = (size_t)(n0 + r) * G4;
        g_xp[base + gA] = a0;
        g_xp[base + gB] = a1;
    }
}

// ---------------- persistent recurrent LSTM layer ----------------
// 128 blocks x 4 batch rows, 256 threads, thread owns gates (2*tid, 2*tid+1).
// Whh^T columns g<384 pinned in smem (192 KB), g>=384 streamed from L2.
// LAYER==0: writes full h sequence to g_h1; LAYER==1: writes only t==T-1 to g_h2.
#define GS 384
#define LSTM_SMEM_FLOATS (128 * GS + 512 + 4 * G4)
#define LSTM_SMEM_BYTES  (LSTM_SMEM_FLOATS * 4)

template<int LAYER>
__global__ void __launch_bounds__(256, 1) lstm_kernel() {
    extern __shared__ float sm[];
    float* ws = sm;                 // [128][GS]   pinned weights (transposed)
    float* hs = sm + 128 * GS;      // [128][4]    h transposed: hs[k*4 + r]
    float* gb = hs + 512;           // [4][512]    activated gates

    const float* wt = (LAYER == 0) ? g_wt0 : g_wt1;
    const int tid  = threadIdx.x;
    const int row0 = blockIdx.x * 4;
    const int g0   = tid * 2;

    for (int i = tid; i < 128 * GS; i += 256) {
        int k = i / GS, g = i % GS;
        ws[i] = wt[k * G4 + g];
    }
    for (int i = tid; i < 512; i += 256) hs[i] = 0.f;
    float c0 = 0.f, c1 = 0.f;
    __syncthreads();

    const int gtype = g0 >> 7;   // 0:i 1:f 2:g 3:o
    const float2* wgp = reinterpret_cast<const float2*>(wt + g0);
    const float2* wsp = reinterpret_cast<const float2*>(ws + g0);

    for (int t = 0; t < TT; t++) {
        // issue xp loads early; folded in AFTER the k-loop so DRAM latency hides
        const float* xprow = g_xp + ((size_t)t * BB + row0) * G4 + g0;
        float2 xv0 = *reinterpret_cast<const float2*>(xprow);
        float2 xv1 = *reinterpret_cast<const float2*>(xprow + 512);
        float2 xv2 = *reinterpret_cast<const float2*>(xprow + 1024);
        float2 xv3 = *reinterpret_cast<const float2*>(xprow + 1536);

        ull a00 = 0ull, a01 = 0ull, a10 = 0ull, a11 = 0ull;
        const ull* hp = reinterpret_cast<const ull*>(hs);

        if (g0 < GS) {
#pragma unroll 8
            for (int k = 0; k < 128; k++) {
                float2 w = wsp[k * (GS / 2)];
                ull w0 = pack2(w.x, w.x), w1 = pack2(w.y, w.y);
                ull h01 = hp[k * 2], h23 = hp[k * 2 + 1];
                a00 = fma2(h01, w0, a00); a01 = fma2(h23, w0, a01);
                a10 = fma2(h01, w1, a10); a11 = fma2(h23, w1, a11);
            }
        } else {
#pragma unroll 8
            for (int k = 0; k < 128; k++) {
                float2 w = wgp[k * (G4 / 2)];
                ull w0 = pack2(w.x, w.x), w1 = pack2(w.y, w.y);
                ull h01 = hp[k * 2], h23 = hp[k * 2 + 1];
                a00 = fma2(h01, w0, a00); a01 = fma2(h23, w0, a01);
                a10 = fma2(h01, w1, a10); a11 = fma2(h23, w1, a11);
            }
        }

        float p00, p01, p02, p03, p10, p11, p12, p13;
        unpack2(a00, p00, p01);  // g0 : rows 0,1
        unpack2(a01, p02, p03);  // g0 : rows 2,3
        unpack2(a10, p10, p11);  // g0+1
        unpack2(a11, p12, p13);
        p00 += xv0.x; p01 += xv1.x; p02 += xv2.x; p03 += xv3.x;
        p10 += xv0.y; p11 += xv1.y; p12 += xv2.y; p13 += xv3.y;

        float q00, q01, q02, q03, q10, q11, q12, q13;
        if (gtype == 2) {
            q00 = ftanh(p00); q01 = ftanh(p01); q02 = ftanh(p02); q03 = ftanh(p03);
            q10 = ftanh(p10); q11 = ftanh(p11); q12 = ftanh(p12); q13 = ftanh(p13);
        } else {
            q00 = fsig(p00); q01 = fsig(p01); q02 = fsig(p02); q03 = fsig(p03);
            q10 = fsig(p10); q11 = fsig(p11); q12 = fsig(p12); q13 = fsig(p13);
        }

        *reinterpret_cast<float2*>(&gb[0 * G4 + g0]) = make_float2(q00, q10);
        *reinterpret_cast<float2*>(&gb[1 * G4 + g0]) = make_float2(q01, q11);
        *reinterpret_cast<float2*>(&gb[2 * G4 + g0]) = make_float2(q02, q12);
        *reinterpret_cast<float2*>(&gb[3 * G4 + g0]) = make_float2(q03, q13);
        __syncthreads();

        // phase 2: c,h update; c lives in registers (thread owns (r,j) = (u>>7, u&127))
        {
            int u = tid, r = u >> 7, j = u & 127;
            float ig = gb[r * G4 + j];
            float fg = gb[r * G4 + 128 + j];
            float gg = gb[r * G4 + 256 + j];
            float og = gb[r * G4 + 384 + j];
            c0 = fg * c0 + ig * gg;
            float h = og * ftanh(c0);
            hs[j * 4 + r] = h;
            if (LAYER == 0) g_h1[((size_t)t * BB + row0 + r) * HH + j] = h;
            else if (t == TT - 1) g_h2[(row0 + r) * HH + j] = h;
        }
        {
            int u = tid + 256, r = u >> 7, j = u & 127;
            float ig = gb[r * G4 + j];
            float fg = gb[r * G4 + 128 + j];
            float gg = gb[r * G4 + 256 + j];
            float og = gb[r * G4 + 384 + j];
            c1 = fg * c1 + ig * gg;
            float h = og * ftanh(c1);
            hs[j * 4 + r] = h;
            if (LAYER == 0) g_h1[((size_t)t * BB + row0 + r) * HH + j] = h;
            else if (t == TT - 1) g_h2[(row0 + r) * HH + j] = h;
        }
        __syncthreads();
    }
}

// ---------------- xproj1 GEMM: g_xp[n][g] = g_h1[n] . Wih1[g] + bsum1[g] ----------------
// 16-row tiles, weights stream from L2 (fully L2-resident, 256 KB), f32x2 accumulation.
__global__ void __launch_bounds__(256, 1) xproj1_kernel() {
    const int AS = 18;               // padded stride for transposed A tile
    __shared__ float as[128 * AS];
    int tid = threadIdx.x;
    size_t m0 = (size_t)blockIdx.x * 16;
    for (int i = tid; i < 16 * 128; i += 256) {
        int r = i >> 7, k = i & 127;
        as[k * AS + r] = g_h1[(m0 + r) * HH + k];
    }
    __syncthreads();

    int g0 = tid * 2;
    float bv0 = g_bsum1[g0], bv1 = g_bsum1[g0 + 1];
    ull acc0[8], acc1[8];
    ull pb0 = pack2(bv0, bv0), pb1 = pack2(bv1, bv1);
#pragma unroll
    for (int p = 0; p < 8; p++) { acc0[p] = pb0; acc1[p] = pb1; }

    const float2* wp = reinterpret_cast<const float2*>(g_wtih1 + g0);
#pragma unroll 4
    for (int k = 0; k < 128; k++) {
        float2 w = wp[k * (G4 / 2)];
        ull w0 = pack2(w.x, w.x), w1 = pack2(w.y, w.y);
        const ull* hrow = reinterpret_cast<const ull*>(&as[k * AS]);
#pragma unroll
        for (int p = 0; p < 8; p++) {
            ull hv = hrow[p];
            acc0[p] = fma2(hv, w0, acc0[p]);
            acc1[p] = fma2(hv, w1, acc1[p]);
        }
    }
#pragma unroll
    for (int p = 0; p < 8; p++) {
        float l0, u0, l1, u1;
        unpack2(acc0[p], l0, u0);
        unpack2(acc1[p], l1, u1);
        size_t base = (m0 + 2 * p) * G4 + g0;
        *reinterpret_cast<float2*>(&g_xp[base])      = make_float2(l0, l1);
        *reinterpret_cast<float2*>(&g_xp[base + G4]) = make_float2(u0, u1);
    }
}

// ---------------- FC head: sigmoid(fc2(relu(fc1(h_last)))) ----------------
__global__ void head_kernel(const float* __restrict__ Wfc1, const float* __restrict__ bfc1,
                            const float* __restrict__ Wfc2, const float* __restrict__ bfc2,
                            float* __restrict__ out) {
    int b = blockIdx.x;
    int u = threadIdx.x;   // 64 threads
    const float* h = g_h2 + b * HH;
    float acc = bfc1[u];
#pragma unroll
    for (int k = 0; k < HH; k++) acc += h[k] * Wfc1[u * HH + k];
    acc = fmaxf(acc, 0.f) * Wfc2[u];
#pragma unroll
    for (int off = 16; off; off >>= 1) acc += __shfl_xor_sync(0xffffffffu, acc, off);
    __shared__ float part[2];
    if ((u & 31) == 0) part[u >> 5] = acc;
    __syncthreads();
    if (u == 0) {
        float s = part[0] + part[1] + bfc2[0];
        out[b] = 1.f / (1.f + expf(-s));
    }
}

// ---------------- launch ----------------
extern "C" void kernel_launch(void* const* d_in, const int* in_sizes, int n_in,
                              void* d_out, int out_size) {
    const float* x     = (const float*)d_in[0];
    const float* Wih0  = (const float*)d_in[1];
    const float* Whh0  = (const float*)d_in[2];
    const float* bih0  = (const float*)d_in[3];
    const float* bhh0  = (const float*)d_in[4];
    const float* Wih1  = (const float*)d_in[5];
    const float* Whh1  = (const float*)d_in[6];
    const float* bih1  = (const float*)d_in[7];
    const float* bhh1  = (const float*)d_in[8];
    const float* Wfc1  = (const float*)d_in[9];
    const float* bfc1  = (const float*)d_in[10];
    const float* Wfc2  = (const float*)d_in[11];
    const float* bfc2  = (const float*)d_in[12];
    float* out = (float*)d_out;

    cudaFuncSetAttribute((const void*)lstm_kernel<0>,
                         cudaFuncAttributeMaxDynamicSharedMemorySize, LSTM_SMEM_BYTES);
    cudaFuncSetAttribute((const void*)lstm_kernel<1>,
                         cudaFuncAttributeMaxDynamicSharedMemorySize, LSTM_SMEM_BYTES);

    prep_kernel<<<256, 256>>>(Whh0, Whh1, Wih1, bih1, bhh1);
    xproj0_kernel<<<(TT * BB) / 16, 256>>>(x, Wih0, bih0, bhh0);
    lstm_kernel<0><<<BB / 4, 256, LSTM_SMEM_BYTES>>>();
    xproj1_kernel<<<(TT * BB) / 16, 256>>>();
    lstm_kernel<1><<<BB / 4, 256, LSTM_SMEM_BYTES>>>();
    head_kernel<<<BB, 64>>>(Wfc1, bfc1, Wfc2, bfc2, out);
}

// round 7
// speedup vs baseline: 1.5064x; 1.5064x over previous
#include <cuda_runtime.h>
#include <cstdint>

#define BB  512
#define TT  512
#define HH  128
#define G4  512
#define NIN 18
#define KREG 56
#define KSM  (128 - KREG)    // 72 k-slices in smem

typedef unsigned long long ull;

// ---------------- scratch (device globals: allocation-free) ----------------
__device__ float g_xp   [(size_t)TT * BB * G4]; // layer-1 input projection
__device__ float g_h1   [(size_t)TT * BB * HH]; // layer-0 hidden sequence
__device__ float g_h2   [BB * HH];              // last hidden of layer 1
__device__ float g_wt0  [HH * G4];              // Whh0 transposed  [k][g]
__device__ float g_wt1  [HH * G4];              // Whh1 transposed  [k][g]
__device__ float g_wtih1[HH * G4];              // Wih1 transposed  [k][g]
__device__ float g_bsum1[G4];                   // bih1 + bhh1

// ---------------- helpers ----------------
__device__ __forceinline__ ull pack2(float lo, float hi) {
    ull r; asm("mov.b64 %0, {%1, %2};" : "=l"(r) : "f"(lo), "f"(hi)); return r;
}
__device__ __forceinline__ void unpack2(ull v, float& lo, float& hi) {
    asm("mov.b64 {%0, %1}, %2;" : "=f"(lo), "=f"(hi) : "l"(v));
}
__device__ __forceinline__ ull fma2(ull a, ull b, ull c) {
    ull d; asm("fma.rn.f32x2 %0, %1, %2, %3;" : "=l"(d) : "l"(a), "l"(b), "l"(c)); return d;
}
__device__ __forceinline__ float fsig(float x)  { return __fdividef(1.f, 1.f + __expf(-x)); }
__device__ __forceinline__ float ftanh(float x) { return __fdividef(2.f, 1.f + __expf(-2.f * x)) - 1.f; }

// ---------------- prep: transposes + fused layer-1 bias ----------------
__global__ void prep_kernel(const float* __restrict__ Whh0, const float* __restrict__ Whh1,
                            const float* __restrict__ Wih1, const float* __restrict__ bih1,
                            const float* __restrict__ bhh1) {
    int idx = blockIdx.x * 256 + threadIdx.x;
    if (idx < G4 * HH) {
        int g = idx / HH, k = idx % HH;
        g_wt0  [k * G4 + g] = Whh0[idx];
        g_wt1  [k * G4 + g] = Whh1[idx];
        g_wtih1[k * G4 + g] = Wih1[idx];
    }
    if (idx < G4) g_bsum1[idx] = bih1[idx] + bhh1[idx];
}

// ---------------- persistent recurrent LSTM layer ----------------
// 128 blocks x 4 batch rows x 256 threads. Thread owns gate pair (2t, 2t+1),
// accumulators are (g0,g1)-packed per row so weights load as raw ull (no packs).
// Whh^T: k<KREG in 112 registers, k>=KREG in 144KB smem. h kept duplicated
// (h,h) in smem for broadcast LDS.128. Layer 0 fuses the 18-dim x-projection
// (Wih0 columns in 36 regs, x double-buffered one step ahead). Layer 1
// prefetches its xp row-slice one step ahead.
#define SM_WS 0
#define SM_HD (KSM * G4)                 // float offset of hd (ull[128][4])
#define SM_GB (SM_HD + 1024)             // gb[4][512]
#define SM_XD (SM_GB + 2048)             // xd: 2*18*4 ull
#define LSTM_SMEM_FLOATS (SM_XD + 288)
#define LSTM_SMEM_BYTES  (LSTM_SMEM_FLOATS * 4)

template<int LAYER>
__global__ void __launch_bounds__(256, 1) lstm_kernel(const float* __restrict__ x,
                                                      const float* __restrict__ Wih0,
                                                      const float* __restrict__ bih0,
                                                      const float* __restrict__ bhh0) {
    extern __shared__ float sm[];
    float* ws = sm + SM_WS;                       // [KSM][512] plain weights
    ull*   hd = reinterpret_cast<ull*>(sm + SM_HD);   // [128][4] duplicated h
    float* gb = sm + SM_GB;                       // [4][512] activated gates
    ull*   xd = reinterpret_cast<ull*>(sm + SM_XD);   // [2][18][4] duplicated x

    const float* wt = (LAYER == 0) ? g_wt0 : g_wt1;
    const int tid  = threadIdx.x;
    const int row0 = blockIdx.x * 4;
    const int g0   = tid * 2;
    const int gtype = g0 >> 7;           // 0:i 1:f 2:g 3:o

    // smem weights k in [KREG,128)
    {
        const ull* src = reinterpret_cast<const ull*>(wt + KREG * G4);
        ull* dst = reinterpret_cast<ull*>(ws);
        for (int i = tid; i < KSM * (G4 / 2); i += 256) dst[i] = src[i];
    }
    // register weight cache k in [0,KREG): (w_g0, w_g1) as one ull each
    ull wreg[KREG];
#pragma unroll
    for (int i = 0; i < KREG; i++)
        wreg[i] = *reinterpret_cast<const ull*>(wt + i * G4 + g0);

    ull wih[NIN];
    ull b01 = 0ull;
    if (LAYER == 0) {
#pragma unroll
        for (int d = 0; d < NIN; d++)
            wih[d] = pack2(Wih0[g0 * NIN + d], Wih0[(g0 + 1) * NIN + d]);
        b01 = pack2(bih0[g0] + bhh0[g0], bih0[g0 + 1] + bhh0[g0 + 1]);
        if (tid < 4 * NIN) {                       // x for t=0
            int r = tid / NIN, d = tid % NIN;
            float v = x[((size_t)(row0 + r) * TT + 0) * NIN + d];
            xd[d * 4 + r] = pack2(v, v);
        }
    }

    for (int i = tid; i < 512; i += 256) hd[i] = 0ull;
    float c0 = 0.f, c1 = 0.f;

    ull xp_cur0 = 0, xp_cur1 = 0, xp_cur2 = 0, xp_cur3 = 0;
    if (LAYER == 1) {
        const ull* xr = reinterpret_cast<const ull*>(g_xp + ((size_t)0 * BB + row0) * G4 + g0);
        xp_cur0 = xr[0]; xp_cur1 = xr[256]; xp_cur2 = xr[512]; xp_cur3 = xr[768];
    }
    __syncthreads();

    for (int t = 0; t < TT; t++) {
        ull a0, a1, a2, a3;
        ull xp_n0 = 0, xp_n1 = 0, xp_n2 = 0, xp_n3 = 0;

        if (LAYER == 1) {
            a0 = xp_cur0; a1 = xp_cur1; a2 = xp_cur2; a3 = xp_cur3;
            if (t + 1 < TT) {   // prefetch next step's xp (hidden under k-loop)
                const ull* xr = reinterpret_cast<const ull*>(
                    g_xp + ((size_t)(t + 1) * BB + row0) * G4 + g0);
                xp_n0 = xr[0]; xp_n1 = xr[256]; xp_n2 = xr[512]; xp_n3 = xr[768];
            }
        } else {
            a0 = b01; a1 = b01; a2 = b01; a3 = b01;
            const ull* xc = xd + (t & 1) * 72;     // fused x-projection (18 dims)
#pragma unroll
            for (int d = 0; d < NIN; d++) {
                ulonglong2 xA = *reinterpret_cast<const ulonglong2*>(xc + d * 4);
                ulonglong2 xB = *reinterpret_cast<const ulonglong2*>(xc + d * 4 + 2);
                a0 = fma2(xA.x, wih[d], a0); a1 = fma2(xA.y, wih[d], a1);
                a2 = fma2(xB.x, wih[d], a2); a3 = fma2(xB.y, wih[d], a3);
            }
            if (t + 1 < TT && tid < 4 * NIN) {     // prefetch x(t+1) into other buffer
                int r = tid / NIN, d = tid % NIN;
                float v = x[((size_t)(row0 + r) * TT + (t + 1)) * NIN + d];
                xd[((t + 1) & 1) * 72 + d * 4 + r] = pack2(v, v);
            }
        }

        // ---- recurrent GEMM: register-cached k ----
#pragma unroll
        for (int k = 0; k < KREG; k++) {
            ulonglong2 hA = *reinterpret_cast<const ulonglong2*>(hd + k * 4);
            ulonglong2 hB = *reinterpret_cast<const ulonglong2*>(hd + k * 4 + 2);
            a0 = fma2(hA.x, wreg[k], a0); a1 = fma2(hA.y, wreg[k], a1);
            a2 = fma2(hB.x, wreg[k], a2); a3 = fma2(hB.y, wreg[k], a3);
        }
        // ---- recurrent GEMM: smem k ----
        {
            const ull* wsp = reinterpret_cast<const ull*>(ws) + tid;
#pragma unroll 8
            for (int k = 0; k < KSM; k++) {
                ull w = wsp[k * 256];
                ulonglong2 hA = *reinterpret_cast<const ulonglong2*>(hd + (KREG + k) * 4);
                ulonglong2 hB = *reinterpret_cast<const ulonglong2*>(hd + (KREG + k) * 4 + 2);
                a0 = fma2(hA.x, w, a0); a1 = fma2(hA.y, w, a1);
                a2 = fma2(hB.x, w, a2); a3 = fma2(hB.y, w, a3);
            }
        }

        float p00, p01, p10, p11, p20, p21, p30, p31;
        unpack2(a0, p00, p01); unpack2(a1, p10, p11);
        unpack2(a2, p20, p21); unpack2(a3, p30, p31);

        float q00, q01, q10, q11, q20, q21, q30, q31;
        if (gtype == 2) {
            q00 = ftanh(p00); q01 = ftanh(p01); q10 = ftanh(p10); q11 = ftanh(p11);
            q20 = ftanh(p20); q21 = ftanh(p21); q30 = ftanh(p30); q31 = ftanh(p31);
        } else {
            q00 = fsig(p00); q01 = fsig(p01); q10 = fsig(p10); q11 = fsig(p11);
            q20 = fsig(p20); q21 = fsig(p21); q30 = fsig(p30); q31 = fsig(p31);
        }
        *reinterpret_cast<float2*>(&gb[0 * G4 + g0]) = make_float2(q00, q01);
        *reinterpret_cast<float2*>(&gb[1 * G4 + g0]) = make_float2(q10, q11);
        *reinterpret_cast<float2*>(&gb[2 * G4 + g0]) = make_float2(q20, q21);
        *reinterpret_cast<float2*>(&gb[3 * G4 + g0]) = make_float2(q30, q31);
        __syncthreads();

        // ---- phase 2: c,h update; thread owns (r,j) ----
        {
            int u = tid, r = u >> 7, j = u & 127;
            float ig = gb[r * G4 + j];
            float fg = gb[r * G4 + 128 + j];
            float gg = gb[r * G4 + 256 + j];
            float og = gb[r * G4 + 384 + j];
            c0 = fg * c0 + ig * gg;
            float h = og * ftanh(c0);
            hd[j * 4 + r] = pack2(h, h);
            if (LAYER == 0) g_h1[((size_t)t * BB + row0 + r) * HH + j] = h;
            else if (t == TT - 1) g_h2[(row0 + r) * HH + j] = h;
        }
        {
            int u = tid + 256, r = u >> 7, j = u & 127;
            float ig = gb[r * G4 + j];
            float fg = gb[r * G4 + 128 + j];
            float gg = gb[r * G4 + 256 + j];
            float og = gb[r * G4 + 384 + j];
            c1 = fg * c1 + ig * gg;
            float h = og * ftanh(c1);
            hd[j * 4 + r] = pack2(h, h);
            if (LAYER == 0) g_h1[((size_t)t * BB + row0 + r) * HH + j] = h;
            else if (t == TT - 1) g_h2[(row0 + r) * HH + j] = h;
        }
        __syncthreads();

        if (LAYER == 1) { xp_cur0 = xp_n0; xp_cur1 = xp_n1; xp_cur2 = xp_n2; xp_cur3 = xp_n3; }
    }
}

// ---------------- xproj1 GEMM: g_xp[n][g] = g_h1[n] . Wih1[g] + bsum1[g] ----------------
// 32-row tiles (8192 blocks), row-pair packed accumulators, weights from L2.
#define XAS 36   // padded float stride (16B-aligned rows for LDS.128)
__global__ void __launch_bounds__(256) xproj1_kernel() {
    __shared__ __align__(16) float as[128 * XAS];
    int tid = threadIdx.x;
    size_t m0 = (size_t)blockIdx.x * 32;
    for (int i = tid; i < 32 * 128; i += 256) {
        int r = i >> 7, k = i & 127;
        as[k * XAS + r] = g_h1[(m0 + r) * HH + k];
    }
    __syncthreads();

    int g0 = tid * 2;
    float bv0 = g_bsum1[g0], bv1 = g_bsum1[g0 + 1];
    ull acc0[16], acc1[16];
    ull pb0 = pack2(bv0, bv0), pb1 = pack2(bv1, bv1);
#pragma unroll
    for (int q = 0; q < 16; q++) { acc0[q] = pb0; acc1[q] = pb1; }

    const float2* wp = reinterpret_cast<const float2*>(g_wtih1) + tid;
#pragma unroll 4
    for (int k = 0; k < 128; k++) {
        float2 w = wp[k * 256];
        ull w0 = pack2(w.x, w.x), w1 = pack2(w.y, w.y);
        const ulonglong2* hrow = reinterpret_cast<const ulonglong2*>(&as[k * XAS]);
#pragma unroll
        for (int p = 0; p < 8; p++) {
            ulonglong2 hv = hrow[p];
            acc0[2 * p]     = fma2(hv.x, w0, acc0[2 * p]);
            acc1[2 * p]     = fma2(hv.x, w1, acc1[2 * p]);
            acc0[2 * p + 1] = fma2(hv.y, w0, acc0[2 * p + 1]);
            acc1[2 * p + 1] = fma2(hv.y, w1, acc1[2 * p + 1]);
        }
    }
#pragma unroll
    for (int q = 0; q < 16; q++) {
        float l0, u0, l1, u1;
        unpack2(acc0[q], l0, u0);
        unpack2(acc1[q], l1, u1);
        size_t base = (m0 + 2 * q) * G4 + g0;
        *reinterpret_cast<float2*>(&g_xp[base])      = make_float2(l0, l1);
        *reinterpret_cast<float2*>(&g_xp[base + G4]) = make_float2(u0, u1);
    }
}

// ---------------- FC head: sigmoid(fc2(relu(fc1(h_last)))) ----------------
__global__ void head_kernel(const float* __restrict__ Wfc1, const float* __restrict__ bfc1,
                            const float* __restrict__ Wfc2, const float* __restrict__ bfc2,
                            float* __restrict__ out) {
    int b = blockIdx.x;
    int u = threadIdx.x;   // 64 threads
    const float* h = g_h2 + b * HH;
    float acc = bfc1[u];
#pragma unroll
    for (int k = 0; k < HH; k++) acc += h[k] * Wfc1[u * HH + k];
    acc = fmaxf(acc, 0.f) * Wfc2[u];
#pragma unroll
    for (int off = 16; off; off >>= 1) acc += __shfl_xor_sync(0xffffffffu, acc, off);
    __shared__ float part[2];
    if ((u & 31) == 0) part[u >> 5] = acc;
    __syncthreads();
    if (u == 0) {
        float s = part[0] + part[1] + bfc2[0];
        out[b] = 1.f / (1.f + expf(-s));
    }
}

// ---------------- launch ----------------
extern "C" void kernel_launch(void* const* d_in, const int* in_sizes, int n_in,
                              void* d_out, int out_size) {
    const float* x     = (const float*)d_in[0];
    const float* Wih0  = (const float*)d_in[1];
    const float* Whh0  = (const float*)d_in[2];
    const float* bih0  = (const float*)d_in[3];
    const float* bhh0  = (const float*)d_in[4];
    const float* Wih1  = (const float*)d_in[5];
    const float* Whh1  = (const float*)d_in[6];
    const float* bih1  = (const float*)d_in[7];
    const float* bhh1  = (const float*)d_in[8];
    const float* Wfc1  = (const float*)d_in[9];
    const float* bfc1  = (const float*)d_in[10];
    const float* Wfc2  = (const float*)d_in[11];
    const float* bfc2  = (const float*)d_in[12];
    float* out = (float*)d_out;

    cudaFuncSetAttribute((const void*)lstm_kernel<0>,
                         cudaFuncAttributeMaxDynamicSharedMemorySize, LSTM_SMEM_BYTES);
    cudaFuncSetAttribute((const void*)lstm_kernel<1>,
                         cudaFuncAttributeMaxDynamicSharedMemorySize, LSTM_SMEM_BYTES);

    prep_kernel<<<256, 256>>>(Whh0, Whh1, Wih1, bih1, bhh1);
    lstm_kernel<0><<<BB / 4, 256, LSTM_SMEM_BYTES>>>(x, Wih0, bih0, bhh0);
    xproj1_kernel<<<(TT * BB) / 32, 256>>>();
    lstm_kernel<1><<<BB / 4, 256, LSTM_SMEM_BYTES>>>(x, Wih0, bih0, bhh0);
    head_kernel<<<BB, 64>>>(Wfc1, bfc1, Wfc2, bfc2, out);
}

// round 8
// speedup vs baseline: 1.6571x; 1.1000x over previous
#include <cuda_runtime.h>
#include <cstdint>

#define BB  512
#define TT  512
#define HH  128
#define G4  512
#define NIN 18

typedef unsigned long long ull;

// ---------------- scratch (device globals: allocation-free) ----------------
__device__ float g_xp   [(size_t)TT * BB * G4]; // reused: xproj0 out, then xproj1 out
__device__ float g_h1   [(size_t)TT * BB * HH]; // layer-0 hidden sequence
__device__ float g_h2   [BB * HH];              // last hidden of layer 1
__device__ float g_wt0  [HH * G4];              // Whh0 transposed  [k][g]
__device__ float g_wt1  [HH * G4];              // Whh1 transposed  [k][g]
__device__ float g_wtih1[HH * G4];              // Wih1 transposed  [k][g]
__device__ float g_bsum1[G4];                   // bih1 + bhh1

// ---------------- helpers ----------------
__device__ __forceinline__ ull pack2(float lo, float hi) {
    ull r; asm("mov.b64 %0, {%1, %2};" : "=l"(r) : "f"(lo), "f"(hi)); return r;
}
__device__ __forceinline__ void unpack2(ull v, float& lo, float& hi) {
    asm("mov.b64 {%0, %1}, %2;" : "=f"(lo), "=f"(hi) : "l"(v));
}
__device__ __forceinline__ ull fma2(ull a, ull b, ull c) {
    ull d; asm("fma.rn.f32x2 %0, %1, %2, %3;" : "=l"(d) : "l"(a), "l"(b), "l"(c)); return d;
}
__device__ __forceinline__ ull add2(ull a, ull b) {
    ull d; asm("add.rn.f32x2 %0, %1, %2;" : "=l"(d) : "l"(a), "l"(b)); return d;
}
__device__ __forceinline__ float fsig(float x)  { return __fdividef(1.f, 1.f + __expf(-x)); }
__device__ __forceinline__ float ftanh(float x) { return __fdividef(2.f, 1.f + __expf(-2.f * x)) - 1.f; }

// ---------------- prep: transposes + fused layer-1 bias ----------------
__global__ void prep_kernel(const float* __restrict__ Whh0, const float* __restrict__ Whh1,
                            const float* __restrict__ Wih1, const float* __restrict__ bih1,
                            const float* __restrict__ bhh1) {
    int idx = blockIdx.x * 256 + threadIdx.x;
    if (idx < G4 * HH) {
        int g = idx / HH, k = idx % HH;
        g_wt0  [k * G4 + g] = Whh0[idx];
        g_wt1  [k * G4 + g] = Whh1[idx];
        g_wtih1[k * G4 + g] = Wih1[idx];
    }
    if (idx < G4) g_bsum1[idx] = bih1[idx] + bhh1[idx];
}

// ---------------- xproj0: g_xp[t][b][g] = x[b][t] . Wih0[g] + bih0[g] + bhh0[g] ----------------
__global__ void __launch_bounds__(256) xproj0_kernel(const float* __restrict__ x,
                                                     const float* __restrict__ Wih0,
                                                     const float* __restrict__ bih0,
                                                     const float* __restrict__ bhh0) {
    __shared__ float wst[NIN][G4];
    __shared__ float bs[G4];
    __shared__ float xs[16][NIN];
    int tid = threadIdx.x;
    for (int i = tid; i < G4 * NIN; i += 256) {
        int g = i / NIN, d = i % NIN;
        wst[d][g] = Wih0[i];
    }
    for (int i = tid; i < G4; i += 256) bs[i] = bih0[i] + bhh0[i];
    int n0 = blockIdx.x * 16;        // n = t*BB + b
    for (int i = tid; i < 16 * NIN; i += 256) {
        int r = i / NIN, d = i % NIN;
        int n = n0 + r;
        int t = n >> 9, b = n & 511;
        xs[r][d] = x[((size_t)b * TT + t) * NIN + d];
    }
    __syncthreads();

    int gA = tid, gB = tid + 256;
    float wA[NIN], wB[NIN];
#pragma unroll
    for (int d = 0; d < NIN; d++) { wA[d] = wst[d][gA]; wB[d] = wst[d][gB]; }
    float bA = bs[gA], bBv = bs[gB];
    for (int r = 0; r < 16; r++) {
        float a0 = bA, a1 = bBv;
#pragma unroll
        for (int d = 0; d < NIN; d++) {
            float xv = xs[r][d];
            a0 += xv * wA[d];
            a1 += xv * wB[d];
        }
        size_t base = (size_t)(n0 + r) * G4;
        g_xp[base + gA] = a0;
        g_xp[base + gB] = a1;
    }
}

// ---------------- persistent recurrent LSTM layer (split-K, 4 gates/thread) ----------------
// 128 blocks x 4 batch rows x 256 threads. lt = tid&127 owns gates 4lt..4lt+3;
// half = tid>>7 accumulates k in [64*half, 64*half+64). Per half, 32 k-slices
// live in registers (128 regs) and 32 stream from smem. h kept duplicated
// (h,h) in smem at ull-stride 6 per k. Upper half dumps partials to smem,
// lower half reduces with add.rn.f32x2, activates, stores gates; phase 2
// updates c,h (c in registers).
#define HDS 6
#define SM_WS  0
#define SM_HD  32768                    // floats; hd = ull[128*HDS]
#define SM_GB  (SM_HD + 128 * HDS * 2)  // 34304: gb[4][512]
#define SM_RED (SM_GB + 2048)           // 36352: red = ull[8*128]
#define LSTM_SMEM_FLOATS (SM_RED + 2048)
#define LSTM_SMEM_BYTES  (LSTM_SMEM_FLOATS * 4)

template<int LAYER>
__global__ void __launch_bounds__(256, 1) lstm_kernel() {
    extern __shared__ float sm[];
    float* ws  = sm + SM_WS;                       // [64 slices][512]
    ull*   hdp = reinterpret_cast<ull*>(sm + SM_HD);
    float* gb  = sm + SM_GB;
    ull*   red = reinterpret_cast<ull*>(sm + SM_RED);

    const float* wt = LAYER ? g_wt1 : g_wt0;
    const int tid  = threadIdx.x;
    const int half = tid >> 7;
    const int lt   = tid & 127;
    const int g0   = lt * 4;
    const int row0 = blockIdx.x * 4;
    const int kb   = half * 64;
    const int gtype = g0 >> 7;          // 0:i 1:f 2:tanh(g) 3:o

    // smem weight slices: s<32 -> k=32+s (lower half), s>=32 -> k=64+s (upper half)
    {
        ull* dst = reinterpret_cast<ull*>(ws);
        for (int i = tid; i < 64 * 256; i += 256) {
            int s = i >> 8, c = i & 255;
            int k = (s < 32) ? (32 + s) : (64 + s);
            dst[i] = reinterpret_cast<const ull*>(wt + (size_t)k * G4)[c];
        }
    }
    // register weight cache: k in [kb, kb+32)
    ull wreg[64];
#pragma unroll
    for (int i = 0; i < 32; i++) {
        ulonglong2 w = *reinterpret_cast<const ulonglong2*>(wt + (size_t)(kb + i) * G4 + g0);
        wreg[2 * i] = w.x; wreg[2 * i + 1] = w.y;
    }
    for (int i = tid; i < 128 * HDS; i += 256) hdp[i] = 0ull;
    float c0 = 0.f, c1 = 0.f;

    float4 xq[4];
    if (half == 0) {
#pragma unroll
        for (int r = 0; r < 4; r++)
            xq[r] = *reinterpret_cast<const float4*>(g_xp + ((size_t)row0 + r) * G4 + g0);
    }
    __syncthreads();

    for (int t = 0; t < TT; t++) {
        ull a[8];
        float4 xn[4];
        if (half == 0) {
#pragma unroll
            for (int r = 0; r < 4; r++) {
                a[2 * r]     = pack2(xq[r].x, xq[r].y);
                a[2 * r + 1] = pack2(xq[r].z, xq[r].w);
            }
            if (t + 1 < TT) {   // prefetch next step's xp; hidden under k-loop
#pragma unroll
                for (int r = 0; r < 4; r++)
                    xn[r] = *reinterpret_cast<const float4*>(
                        g_xp + ((size_t)(t + 1) * BB + row0 + r) * G4 + g0);
            }
        } else {
#pragma unroll
            for (int q = 0; q < 8; q++) a[q] = 0ull;
        }

        // ---- k in [kb, kb+32): register weights ----
#pragma unroll
        for (int i = 0; i < 32; i++) {
            int k = kb + i;
            ulonglong2 hA = *reinterpret_cast<const ulonglong2*>(hdp + k * HDS);
            ulonglong2 hB = *reinterpret_cast<const ulonglong2*>(hdp + k * HDS + 2);
            a[0] = fma2(hA.x, wreg[2 * i], a[0]); a[1] = fma2(hA.x, wreg[2 * i + 1], a[1]);
            a[2] = fma2(hA.y, wreg[2 * i], a[2]); a[3] = fma2(hA.y, wreg[2 * i + 1], a[3]);
            a[4] = fma2(hB.x, wreg[2 * i], a[4]); a[5] = fma2(hB.x, wreg[2 * i + 1], a[5]);
            a[6] = fma2(hB.y, wreg[2 * i], a[6]); a[7] = fma2(hB.y, wreg[2 * i + 1], a[7]);
        }
        // ---- k in [kb+32, kb+64): smem weights ----
        {
            const ull* wsp = reinterpret_cast<const ull*>(ws) + (size_t)(half * 32) * 256 + lt * 2;
#pragma unroll 8
            for (int s = 0; s < 32; s++) {
                int k = kb + 32 + s;
                ulonglong2 wv = *reinterpret_cast<const ulonglong2*>(wsp + s * 256);
                ulonglong2 hA = *reinterpret_cast<const ulonglong2*>(hdp + k * HDS);
                ulonglong2 hB = *reinterpret_cast<const ulonglong2*>(hdp + k * HDS + 2);
                a[0] = fma2(hA.x, wv.x, a[0]); a[1] = fma2(hA.x, wv.y, a[1]);
                a[2] = fma2(hA.y, wv.x, a[2]); a[3] = fma2(hA.y, wv.y, a[3]);
                a[4] = fma2(hB.x, wv.x, a[4]); a[5] = fma2(hB.x, wv.y, a[5]);
                a[6] = fma2(hB.y, wv.x, a[6]); a[7] = fma2(hB.y, wv.y, a[7]);
            }
        }

        // ---- split-K reduce + activation (lower half finalizes) ----
        if (half == 1) {
#pragma unroll
            for (int q = 0; q < 8; q++) red[q * 128 + lt] = a[q];
        }
        __syncthreads();
        if (half == 0) {
#pragma unroll
            for (int q = 0; q < 8; q++) a[q] = add2(a[q], red[q * 128 + lt]);
            float p[16], v[16];
#pragma unroll
            for (int q = 0; q < 8; q++) unpack2(a[q], p[2 * q], p[2 * q + 1]);
            if (gtype == 2) {
#pragma unroll
                for (int i = 0; i < 16; i++) v[i] = ftanh(p[i]);
            } else {
#pragma unroll
                for (int i = 0; i < 16; i++) v[i] = fsig(p[i]);
            }
#pragma unroll
            for (int r = 0; r < 4; r++)
                *reinterpret_cast<float4*>(&gb[r * G4 + g0]) =
                    make_float4(v[4 * r], v[4 * r + 1], v[4 * r + 2], v[4 * r + 3]);
        }
        __syncthreads();

        // ---- phase 2: c,h update; thread owns 2 (r,j) items ----
        {
            int r = tid >> 7, j = tid & 127;
            float ig = gb[r * G4 + j];
            float fg = gb[r * G4 + 128 + j];
            float gg = gb[r * G4 + 256 + j];
            float og = gb[r * G4 + 384 + j];
            c0 = fg * c0 + ig * gg;
            float h = og * ftanh(c0);
            hdp[j * HDS + r] = pack2(h, h);
            if (LAYER == 0) g_h1[((size_t)t * BB + row0 + r) * HH + j] = h;
            else if (t == TT - 1) g_h2[(row0 + r) * HH + j] = h;
        }
        {
            int u = tid + 256; int r = u >> 7, j = u & 127;
            float ig = gb[r * G4 + j];
            float fg = gb[r * G4 + 128 + j];
            float gg = gb[r * G4 + 256 + j];
            float og = gb[r * G4 + 384 + j];
            c1 = fg * c1 + ig * gg;
            float h = og * ftanh(c1);
            hdp[j * HDS + r] = pack2(h, h);
            if (LAYER == 0) g_h1[((size_t)t * BB + row0 + r) * HH + j] = h;
            else if (t == TT - 1) g_h2[(row0 + r) * HH + j] = h;
        }
        __syncthreads();

        if (half == 0 && t + 1 < TT) {
#pragma unroll
            for (int r = 0; r < 4; r++) xq[r] = xn[r];
        }
    }
}

// ---------------- xproj1 GEMM: g_xp[n][g] = g_h1[n] . Wih1[g] + bsum1[g] ----------------
#define XAS 36
__global__ void __launch_bounds__(256) xproj1_kernel() {
    __shared__ __align__(16) float as[128 * XAS];
    int tid = threadIdx.x;
    size_t m0 = (size_t)blockIdx.x * 32;
    for (int i = tid; i < 32 * 128; i += 256) {
        int r = i >> 7, k = i & 127;
        as[k * XAS + r] = g_h1[(m0 + r) * HH + k];
    }
    __syncthreads();

    int g0 = tid * 2;
    float bv0 = g_bsum1[g0], bv1 = g_bsum1[g0 + 1];
    ull acc0[16], acc1[16];
    ull pb0 = pack2(bv0, bv0), pb1 = pack2(bv1, bv1);
#pragma unroll
    for (int q = 0; q < 16; q++) { acc0[q] = pb0; acc1[q] = pb1; }

    const float2* wp = reinterpret_cast<const float2*>(g_wtih1) + tid;
#pragma unroll 4
    for (int k = 0; k < 128; k++) {
        float2 w = wp[k * 256];
        ull w0 = pack2(w.x, w.x), w1 = pack2(w.y, w.y);
        const ulonglong2* hrow = reinterpret_cast<const ulonglong2*>(&as[k * XAS]);
#pragma unroll
        for (int p = 0; p < 8; p++) {
            ulonglong2 hv = hrow[p];
            acc0[2 * p]     = fma2(hv.x, w0, acc0[2 * p]);
            acc1[2 * p]     = fma2(hv.x, w1, acc1[2 * p]);
            acc0[2 * p + 1] = fma2(hv.y, w0, acc0[2 * p + 1]);
            acc1[2 * p + 1] = fma2(hv.y, w1, acc1[2 * p + 1]);
        }
    }
#pragma unroll
    for (int q = 0; q < 16; q++) {
        float l0, u0, l1, u1;
        unpack2(acc0[q], l0, u0);
        unpack2(acc1[q], l1, u1);
        size_t base = (m0 + 2 * q) * G4 + g0;
        *reinterpret_cast<float2*>(&g_xp[base])      = make_float2(l0, l1);
        *reinterpret_cast<float2*>(&g_xp[base + G4]) = make_float2(u0, u1);
    }
}

// ---------------- FC head ----------------
__global__ void head_kernel(const float* __restrict__ Wfc1, const float* __restrict__ bfc1,
                            const float* __restrict__ Wfc2, const float* __restrict__ bfc2,
                            float* __restrict__ out) {
    int b = blockIdx.x;
    int u = threadIdx.x;   // 64 threads
    const float* h = g_h2 + b * HH;
    float acc = bfc1[u];
#pragma unroll
    for (int k = 0; k < HH; k++) acc += h[k] * Wfc1[u * HH + k];
    acc = fmaxf(acc, 0.f) * Wfc2[u];
#pragma unroll
    for (int off = 16; off; off >>= 1) acc += __shfl_xor_sync(0xffffffffu, acc, off);
    __shared__ float part[2];
    if ((u & 31) == 0) part[u >> 5] = acc;
    __syncthreads();
    if (u == 0) {
        float s = part[0] + part[1] + bfc2[0];
        out[b] = 1.f / (1.f + expf(-s));
    }
}

// ---------------- launch ----------------
extern "C" void kernel_launch(void* const* d_in, const int* in_sizes, int n_in,
                              void* d_out, int out_size) {
    const float* x     = (const float*)d_in[0];
    const float* Wih0  = (const float*)d_in[1];
    const float* Whh0  = (const float*)d_in[2];
    const float* bih0  = (const float*)d_in[3];
    const float* bhh0  = (const float*)d_in[4];
    const float* Wih1  = (const float*)d_in[5];
    const float* Whh1  = (const float*)d_in[6];
    const float* bih1  = (const float*)d_in[7];
    const float* bhh1  = (const float*)d_in[8];
    const float* Wfc1  = (const float*)d_in[9];
    const float* bfc1  = (const float*)d_in[10];
    const float* Wfc2  = (const float*)d_in[11];
    const float* bfc2  = (const float*)d_in[12];
    float* out = (float*)d_out;

    cudaFuncSetAttribute((const void*)lstm_kernel<0>,
                         cudaFuncAttributeMaxDynamicSharedMemorySize, LSTM_SMEM_BYTES);
    cudaFuncSetAttribute((const void*)lstm_kernel<1>,
                         cudaFuncAttributeMaxDynamicSharedMemorySize, LSTM_SMEM_BYTES);

    prep_kernel<<<256, 256>>>(Whh0, Whh1, Wih1, bih1, bhh1);
    xproj0_kernel<<<(TT * BB) / 16, 256>>>(x, Wih0, bih0, bhh0);
    lstm_kernel<0><<<BB / 4, 256, LSTM_SMEM_BYTES>>>();
    xproj1_kernel<<<(TT * BB) / 32, 256>>>();
    lstm_kernel<1><<<BB / 4, 256, LSTM_SMEM_BYTES>>>();
    head_kernel<<<BB, 64>>>(Wfc1, bfc1, Wfc2, bfc2, out);
}

// round 9
// speedup vs baseline: 1.7343x; 1.0466x over previous
#include <cuda_runtime.h>
#include <cstdint>

#define BB  512
#define TT  512
#define HH  128
#define G4  512
#define NIN 18

typedef unsigned long long ull;

// All gate-indexed arrays use the permuted order g' = j*4 + type,
// where original g = type*128 + j  (type: 0=i 1=f 2=g 3=o).
__device__ __forceinline__ int orig_gate(int gp) { return (gp & 3) * 128 + (gp >> 2); }

// ---------------- scratch (device globals: allocation-free) ----------------
__device__ float g_xp   [(size_t)TT * BB * G4]; // projections, permuted gate order
__device__ float g_h1   [(size_t)TT * BB * HH]; // layer-0 hidden sequence [t][b][j]
__device__ float g_h2   [BB * HH];              // last hidden of layer 1 [b][j]
__device__ float g_wt0  [HH * G4];              // Whh0^T  [k][g']
__device__ float g_wt1  [HH * G4];              // Whh1^T  [k][g']
__device__ float g_wtih1[HH * G4];              // Wih1^T  [k][g']
__device__ float g_bsum1[G4];                   // (bih1 + bhh1)[g']

// ---------------- helpers ----------------
__device__ __forceinline__ ull pack2(float lo, float hi) {
    ull r; asm("mov.b64 %0, {%1, %2};" : "=l"(r) : "f"(lo), "f"(hi)); return r;
}
__device__ __forceinline__ void unpack2(ull v, float& lo, float& hi) {
    asm("mov.b64 {%0, %1}, %2;" : "=f"(lo), "=f"(hi) : "l"(v));
}
__device__ __forceinline__ ull fma2(ull a, ull b, ull c) {
    ull d; asm("fma.rn.f32x2 %0, %1, %2, %3;" : "=l"(d) : "l"(a), "l"(b), "l"(c)); return d;
}
__device__ __forceinline__ ull add2(ull a, ull b) {
    ull d; asm("add.rn.f32x2 %0, %1, %2;" : "=l"(d) : "l"(a), "l"(b)); return d;
}

// ---------------- prep: permuted transposes + fused layer-1 bias ----------------
__global__ void prep_kernel(const float* __restrict__ Whh0, const float* __restrict__ Whh1,
                            const float* __restrict__ Wih1, const float* __restrict__ bih1,
                            const float* __restrict__ bhh1) {
    int idx = blockIdx.x * 256 + threadIdx.x;
    if (idx < G4 * HH) {
        int gp = idx / HH, k = idx % HH;
        int go = orig_gate(gp);
        g_wt0  [k * G4 + gp] = Whh0[go * HH + k];
        g_wt1  [k * G4 + gp] = Whh1[go * HH + k];
        g_wtih1[k * G4 + gp] = Wih1[go * HH + k];
    }
    if (idx < G4) {
        int go = orig_gate(idx);
        g_bsum1[idx] = bih1[go] + bhh1[go];
    }
}

// ---------------- xproj0 (permuted output) ----------------
__global__ void __launch_bounds__(256) xproj0_kernel(const float* __restrict__ x,
                                                     const float* __restrict__ Wih0,
                                                     const float* __restrict__ bih0,
                                                     const float* __restrict__ bhh0) {
    __shared__ float wst[NIN][G4];
    __shared__ float bs[G4];
    __shared__ float xs[16][NIN];
    int tid = threadIdx.x;
    for (int i = tid; i < G4 * NIN; i += 256) {
        int g = i / NIN, d = i % NIN;
        wst[d][g] = Wih0[orig_gate(g) * NIN + d];
    }
    for (int i = tid; i < G4; i += 256) {
        int go = orig_gate(i);
        bs[i] = bih0[go] + bhh0[go];
    }
    int n0 = blockIdx.x * 16;        // n = t*BB + b
    for (int i = tid; i < 16 * NIN; i += 256) {
        int r = i / NIN, d = i % NIN;
        int n = n0 + r;
        int t = n >> 9, b = n & 511;
        xs[r][d] = x[((size_t)b * TT + t) * NIN + d];
    }
    __syncthreads();

    int gA = tid, gB = tid + 256;
    float wA[NIN], wB[NIN];
#pragma unroll
    for (int d = 0; d < NIN; d++) { wA[d] = wst[d][gA]; wB[d] = wst[d][gB]; }
    float bA = bs[gA], bBv = bs[gB];
    for (int r = 0; r < 16; r++) {
        float a0 = bA, a1 = bBv;
#pragma unroll
        for (int d = 0; d < NIN; d++) {
            float xv = xs[r][d];
            a0 += xv * wA[d];
            a1 += xv * wB[d];
        }
        size_t base = (size_t)(n0 + r) * G4;
        g_xp[base + gA] = a0;
        g_xp[base + gB] = a1;
    }
}

// ---------------- persistent recurrent LSTM layer ----------------
// 128 blocks x 4 rows x 256 threads. lt=tid&127 owns gates 4lt..4lt+3 (=column
// j=lt, types i,f,g,o thanks to the j-major permutation); half=tid>>7 owns
// k in [64*half, 64*half+64). Per half: 32 k-slices as DUPLICATED weights in
// 128 registers (row-packed accs, single broadcast LDS.128 of natural h), and
// 32 k-slices streamed from smem (gate-packed accs, duplicated-h broadcasts).
// Upper half prefetches next-step xp into a parity-buffered smem xbuf and dumps
// split-K partials to red; lower half reduces, activates (fused rationals),
// updates c (registers) and h, writing hnat (float4) + hd (duplicated).
#define SM_WS  0                         // ws[64][512] floats (128KB)
#define SM_HD  32768                     // hd: ull[128][6] -> 1536 floats
#define SM_HN  (SM_HD + 1536)            // hnat: float4[128] -> 512 floats
#define SM_RED (SM_HN + 512)             // red: ull[8][128] -> 2048 floats
#define SM_XB  (SM_RED + 2048)           // xbuf: [2][4][512] floats
#define LSTM_SMEM_FLOATS (SM_XB + 4096)
#define LSTM_SMEM_BYTES  (LSTM_SMEM_FLOATS * 4)

template<int LAYER>
__global__ void __launch_bounds__(256, 1) lstm_kernel() {
    extern __shared__ float sm[];
    float* ws   = sm + SM_WS;
    ull*   hdp  = reinterpret_cast<ull*>(sm + SM_HD);
    float* hnat = sm + SM_HN;
    ull*   redp = reinterpret_cast<ull*>(sm + SM_RED);
    float* xbuf = sm + SM_XB;

    const float* wt = LAYER ? g_wt1 : g_wt0;
    const int tid  = threadIdx.x;
    const int half = tid >> 7;
    const int lt   = tid & 127;
    const int g0   = lt * 4;
    const int row0 = blockIdx.x * 4;
    const int kb   = half * 64;

    // smem weight slices: s in [0,32) -> k=32+s ; s in [32,64) -> k=64+s
    {
        ull* dst = reinterpret_cast<ull*>(ws);
        for (int i = tid; i < 64 * 256; i += 256) {
            int s = i >> 8, c = i & 255;
            int k = (s < 32) ? (32 + s) : (64 + s);
            dst[i] = reinterpret_cast<const ull*>(wt + (size_t)k * G4)[c];
        }
    }
    // duplicated register weight cache: k in [kb, kb+32), 4 ull per k
    ull wd[128];
#pragma unroll
    for (int i = 0; i < 32; i++) {
        float4 w4 = *reinterpret_cast<const float4*>(wt + (size_t)(kb + i) * G4 + g0);
        wd[4 * i + 0] = pack2(w4.x, w4.x);
        wd[4 * i + 1] = pack2(w4.y, w4.y);
        wd[4 * i + 2] = pack2(w4.z, w4.z);
        wd[4 * i + 3] = pack2(w4.w, w4.w);
    }
    // zero h state; stage xp(t=0) into xbuf[0]
    for (int i = tid; i < 1536 + 512; i += 256) sm[SM_HD + i] = 0.f;
    for (int i = tid; i < 2048; i += 256) {
        int r = i >> 9, g = i & 511;
        xbuf[i] = g_xp[((size_t)0 * BB + row0 + r) * G4 + g];
    }
    float c0 = 0.f, c1 = 0.f, c2 = 0.f, c3 = 0.f;
    __syncthreads();

    const ull* wsp = reinterpret_cast<const ull*>(ws) + (size_t)(half * 32) * 256 + lt * 2;

    for (int t = 0; t < TT; t++) {
        ull aG[8], aR[8];
        float4 xn0, xn1, xn2, xn3;
        if (half == 0) {
            const float* xb = xbuf + (t & 1) * 2048 + g0;
#pragma unroll
            for (int r = 0; r < 4; r++) {
                float4 xv = *reinterpret_cast<const float4*>(xb + r * 512);
                aG[2 * r]     = pack2(xv.x, xv.y);
                aG[2 * r + 1] = pack2(xv.z, xv.w);
            }
        } else {
#pragma unroll
            for (int q = 0; q < 8; q++) aG[q] = 0ull;
            if (t + 1 < TT) {   // upper prefetches next step's xp
                const float* xr = g_xp + ((size_t)(t + 1) * BB + row0) * G4 + g0;
                xn0 = *reinterpret_cast<const float4*>(xr);
                xn1 = *reinterpret_cast<const float4*>(xr + 512);
                xn2 = *reinterpret_cast<const float4*>(xr + 1024);
                xn3 = *reinterpret_cast<const float4*>(xr + 1536);
            }
        }
#pragma unroll
        for (int q = 0; q < 8; q++) aR[q] = 0ull;

        // ---- reg-k: row-packed accs, duplicated reg weights, natural h ----
#pragma unroll
        for (int i = 0; i < 32; i++) {
            int k = kb + i;
            ulonglong2 hn = *reinterpret_cast<const ulonglong2*>(hnat + k * 4);
            aR[0] = fma2(hn.x, wd[4 * i + 0], aR[0]); aR[1] = fma2(hn.y, wd[4 * i + 0], aR[1]);
            aR[2] = fma2(hn.x, wd[4 * i + 1], aR[2]); aR[3] = fma2(hn.y, wd[4 * i + 1], aR[3]);
            aR[4] = fma2(hn.x, wd[4 * i + 2], aR[4]); aR[5] = fma2(hn.y, wd[4 * i + 2], aR[5]);
            aR[6] = fma2(hn.x, wd[4 * i + 3], aR[6]); aR[7] = fma2(hn.y, wd[4 * i + 3], aR[7]);
        }
        // ---- smem-k: gate-packed accs, undup smem weights, duplicated h ----
#pragma unroll 8
        for (int s = 0; s < 32; s++) {
            int k = kb + 32 + s;
            ulonglong2 wv = *reinterpret_cast<const ulonglong2*>(wsp + s * 256);
            ulonglong2 hA = *reinterpret_cast<const ulonglong2*>(hdp + k * 6);
            ulonglong2 hB = *reinterpret_cast<const ulonglong2*>(hdp + k * 6 + 2);
            aG[0] = fma2(hA.x, wv.x, aG[0]); aG[1] = fma2(hA.x, wv.y, aG[1]);
            aG[2] = fma2(hA.y, wv.x, aG[2]); aG[3] = fma2(hA.y, wv.y, aG[3]);
            aG[4] = fma2(hB.x, wv.x, aG[4]); aG[5] = fma2(hB.x, wv.y, aG[5]);
            aG[6] = fma2(hB.y, wv.x, aG[6]); aG[7] = fma2(hB.y, wv.y, aG[7]);
        }

        // ---- fold row-packed into gate-packed ----
        {
            float rv0, rv1, rv2, rv3, rw0, rw1, rw2, rw3;
            unpack2(aR[0], rv0, rv1); unpack2(aR[1], rv2, rv3);   // gate q0, rows 0..3
            float sv0, sv1, sv2, sv3;
            unpack2(aR[2], sv0, sv1); unpack2(aR[3], sv2, sv3);   // gate q1
            float tv0, tv1, tv2, tv3;
            unpack2(aR[4], tv0, tv1); unpack2(aR[5], tv2, tv3);   // gate q2
            unpack2(aR[6], rw0, rw1); unpack2(aR[7], rw2, rw3);   // gate q3
            aG[0] = add2(aG[0], pack2(rv0, sv0)); aG[1] = add2(aG[1], pack2(tv0, rw0));
            aG[2] = add2(aG[2], pack2(rv1, sv1)); aG[3] = add2(aG[3], pack2(tv1, rw1));
            aG[4] = add2(aG[4], pack2(rv2, sv2)); aG[5] = add2(aG[5], pack2(tv2, rw2));
            aG[6] = add2(aG[6], pack2(rv3, sv3)); aG[7] = add2(aG[7], pack2(tv3, rw3));
        }

        if (half == 1) {
#pragma unroll
            for (int q = 0; q < 8; q++) redp[q * 128 + lt] = aG[q];
            if (t + 1 < TT) {
                float* xb = xbuf + ((t + 1) & 1) * 2048 + g0;
                *reinterpret_cast<float4*>(xb)        = xn0;
                *reinterpret_cast<float4*>(xb + 512)  = xn1;
                *reinterpret_cast<float4*>(xb + 1024) = xn2;
                *reinterpret_cast<float4*>(xb + 1536) = xn3;
            }
        }
        __syncthreads();   // B1: partials + xbuf visible

        if (half == 0) {
#pragma unroll
            for (int q = 0; q < 8; q++) aG[q] = add2(aG[q], redp[q * 128 + lt]);
            float v[4][4];
#pragma unroll
            for (int r = 0; r < 4; r++) {
                unpack2(aG[2 * r],     v[r][0], v[r][1]);
                unpack2(aG[2 * r + 1], v[r][2], v[r][3]);
            }
            float h[4];
            float* cp[4] = {&c0, &c1, &c2, &c3};
#pragma unroll
            for (int r = 0; r < 4; r++) {
                float ei = __expf(-v[r][0]);
                float ef = __expf(-v[r][1]);
                float eg = __expf(-2.f * v[r][2]);
                float eo = __expf(-v[r][3]);
                float fg = __fdividef(1.f, 1.f + ef);
                float ig = __fdividef(1.f - eg, (1.f + ei) * (1.f + eg));  // sig(i)*tanh(g)
                float c  = fg * (*cp[r]) + ig;
                *cp[r] = c;
                float ec = __expf(-2.f * c);
                float th = __fdividef(2.f, 1.f + ec) - 1.f;                 // safe tanh(c)
                float so = __fdividef(1.f, 1.f + eo);
                h[r] = so * th;
            }
            *reinterpret_cast<float4*>(hnat + lt * 4) = make_float4(h[0], h[1], h[2], h[3]);
            ulonglong2 d01; d01.x = pack2(h[0], h[0]); d01.y = pack2(h[1], h[1]);
            ulonglong2 d23; d23.x = pack2(h[2], h[2]); d23.y = pack2(h[3], h[3]);
            *reinterpret_cast<ulonglong2*>(hdp + lt * 6)     = d01;
            *reinterpret_cast<ulonglong2*>(hdp + lt * 6 + 2) = d23;
            if (LAYER == 0) {
#pragma unroll
                for (int r = 0; r < 4; r++)
                    g_h1[((size_t)t * BB + row0 + r) * HH + lt] = h[r];
            } else if (t == TT - 1) {
#pragma unroll
                for (int r = 0; r < 4; r++)
                    g_h2[(row0 + r) * HH + lt] = h[r];
            }
        }
        __syncthreads();   // B2: h state visible for next step
    }
}

// ---------------- xproj1 GEMM (unchanged; arrays pre-permuted) ----------------
#define XAS 36
__global__ void __launch_bounds__(256) xproj1_kernel() {
    __shared__ __align__(16) float as[128 * XAS];
    int tid = threadIdx.x;
    size_t m0 = (size_t)blockIdx.x * 32;
    for (int i = tid; i < 32 * 128; i += 256) {
        int r = i >> 7, k = i & 127;
        as[k * XAS + r] = g_h1[(m0 + r) * HH + k];
    }
    __syncthreads();

    int g0 = tid * 2;
    float bv0 = g_bsum1[g0], bv1 = g_bsum1[g0 + 1];
    ull acc0[16], acc1[16];
    ull pb0 = pack2(bv0, bv0), pb1 = pack2(bv1, bv1);
#pragma unroll
    for (int q = 0; q < 16; q++) { acc0[q] = pb0; acc1[q] = pb1; }

    const float2* wp = reinterpret_cast<const float2*>(g_wtih1) + tid;
#pragma unroll 4
    for (int k = 0; k < 128; k++) {
        float2 w = wp[k * 256];
        ull w0 = pack2(w.x, w.x), w1 = pack2(w.y, w.y);
        const ulonglong2* hrow = reinterpret_cast<const ulonglong2*>(&as[k * XAS]);
#pragma unroll
        for (int p = 0; p < 8; p++) {
            ulonglong2 hv = hrow[p];
            acc0[2 * p]     = fma2(hv.x, w0, acc0[2 * p]);
            acc1[2 * p]     = fma2(hv.x, w1, acc1[2 * p]);
            acc0[2 * p + 1] = fma2(hv.y, w0, acc0[2 * p + 1]);
            acc1[2 * p + 1] = fma2(hv.y, w1, acc1[2 * p + 1]);
        }
    }
#pragma unroll
    for (int q = 0; q < 16; q++) {
        float l0, u0, l1, u1;
        unpack2(acc0[q], l0, u0);
        unpack2(acc1[q], l1, u1);
        size_t base = (m0 + 2 * q) * G4 + g0;
        *reinterpret_cast<float2*>(&g_xp[base])      = make_float2(l0, l1);
        *reinterpret_cast<float2*>(&g_xp[base + G4]) = make_float2(u0, u1);
    }
}

// ---------------- FC head ----------------
__global__ void head_kernel(const float* __restrict__ Wfc1, const float* __restrict__ bfc1,
                            const float* __restrict__ Wfc2, const float* __restrict__ bfc2,
                            float* __restrict__ out) {
    int b = blockIdx.x;
    int u = threadIdx.x;   // 64 threads
    const float* h = g_h2 + b * HH;
    float acc = bfc1[u];
#pragma unroll
    for (int k = 0; k < HH; k++) acc += h[k] * Wfc1[u * HH + k];
    acc = fmaxf(acc, 0.f) * Wfc2[u];
#pragma unroll
    for (int off = 16; off; off >>= 1) acc += __shfl_xor_sync(0xffffffffu, acc, off);
    __shared__ float part[2];
    if ((u & 31) == 0) part[u >> 5] = acc;
    __syncthreads();
    if (u == 0) {
        float s = part[0] + part[1] + bfc2[0];
        out[b] = 1.f / (1.f + expf(-s));
    }
}

// ---------------- launch ----------------
extern "C" void kernel_launch(void* const* d_in, const int* in_sizes, int n_in,
                              void* d_out, int out_size) {
    const float* x     = (const float*)d_in[0];
    const float* Wih0  = (const float*)d_in[1];
    const float* Whh0  = (const float*)d_in[2];
    const float* bih0  = (const float*)d_in[3];
    const float* bhh0  = (const float*)d_in[4];
    const float* Wih1  = (const float*)d_in[5];
    const float* Whh1  = (const float*)d_in[6];
    const float* bih1  = (const float*)d_in[7];
    const float* bhh1  = (const float*)d_in[8];
    const float* Wfc1  = (const float*)d_in[9];
    const float* bfc1  = (const float*)d_in[10];
    const float* Wfc2  = (const float*)d_in[11];
    const float* bfc2  = (const float*)d_in[12];
    float* out = (float*)d_out;

    cudaFuncSetAttribute((const void*)lstm_kernel<0>,
                         cudaFuncAttributeMaxDynamicSharedMemorySize, LSTM_SMEM_BYTES);
    cudaFuncSetAttribute((const void*)lstm_kernel<1>,
                         cudaFuncAttributeMaxDynamicSharedMemorySize, LSTM_SMEM_BYTES);

    prep_kernel<<<256, 256>>>(Whh0, Whh1, Wih1, bih1, bhh1);
    xproj0_kernel<<<(TT * BB) / 16, 256>>>(x, Wih0, bih0, bhh0);
    lstm_kernel<0><<<BB / 4, 256, LSTM_SMEM_BYTES>>>();
    xproj1_kernel<<<(TT * BB) / 32, 256>>>();
    lstm_kernel<1><<<BB / 4, 256, LSTM_SMEM_BYTES>>>();
    head_kernel<<<BB, 64>>>(Wfc1, bfc1, Wfc2, bfc2, out);
}